// round 11
// baseline (speedup 1.0000x reference)
#include <cuda_runtime.h>
#include <cstddef>

// Problem constants (fixed by the reference)
#define NN 50000
#define EE 800000
#define IND 256
#define HID 128
#define NE4 ((EE / 4 + 255) / 256)   // 782 edge blocks, 4 edges/thread
#define NBG (NN / 16)                // 3125 gemv blocks, 16 rows/block (half-warp per row)

// ---------------- scratch (no allocation allowed) ----------------
__device__ int   g_is64;          // 1 if edge_index is int64, 0 if int32
__device__ float g_deg[NN];
__device__ float g_dinv[NN];
__device__ float g_t[NN];         // t = x @ u  (raw)
__device__ float g_tt[NN];        // tt = dinv * t
__device__ float g_s[NN];         // scatter1 accumulator (raw)
__device__ float g_ss[NN];        // ss = dinv * s_final
__device__ float g_z[NN];         // scatter2 accumulator (raw)
__device__ float g_u[IND];        // u = W1 @ (W2 @ Wc)
__device__ float g_b1v;           // b1 . v
__device__ float g_b2c;           // b2 . Wc + bc

__device__ __forceinline__ int edge_src64(const int* p, int e) { return p[2 * e]; }
__device__ __forceinline__ int edge_dst64(const int* p, int e) { return p[2 * (EE + e)]; }

__device__ __forceinline__ float warp_reduce(float v) {
#pragma unroll
    for (int off = 16; off > 0; off >>= 1)
        v += __shfl_xor_sync(0xFFFFFFFFu, v, off);
    return v;
}
__device__ __forceinline__ float half_reduce(float v) {   // reduce within 16-lane group
#pragma unroll
    for (int off = 8; off > 0; off >>= 1)
        v += __shfl_xor_sync(0xFFFFFFFFu, v, off);
    return v;
}

// ---------------- init + dtype probe (block 0) ----------------
__global__ void init_kernel(const int* __restrict__ ei) {
    int i = blockIdx.x * blockDim.x + threadIdx.x;
    if (i < NN) {
        g_deg[i] = 1.0f;   // self-loop weight
        g_s[i] = 0.0f;
        g_z[i] = 0.0f;
    }
    if (blockIdx.x == 0) {
        __shared__ int nz;
        if (threadIdx.x == 0) nz = 0;
        __syncthreads();
        int v = ei[2 * threadIdx.x + 1];   // odd words: 0 iff int64 layout
        if (v != 0) atomicAdd(&nz, 1);
        __syncthreads();
        if (threadIdx.x == 0) g_is64 = (nz < 8) ? 1 : 0;
    }
}

// ---------------- fused weight collapse: u = W1@(W2@Wc), scalars ----------------
// One block, 256 threads = 8 warps. Warp-parallel row dots (NOT serial per-thread).
__global__ void weights_kernel(const float* __restrict__ W1,
                               const float* __restrict__ b1,
                               const float* __restrict__ W2,
                               const float* __restrict__ b2,
                               const float* __restrict__ Wc,
                               const float* __restrict__ bc) {
    __shared__ float sv[HID];
    int wid = threadIdx.x >> 5;
    int lane = threadIdx.x & 31;

    // stage 1: v[r] = W2[r,:].Wc   (8 warps x 16 rows each)
    for (int r = wid; r < HID; r += 8) {
        const float* row = W2 + (size_t)r * HID;
        float acc = 0.0f;
#pragma unroll
        for (int i = 0; i < 4; i++) { int k = lane + i * 32; acc += row[k] * Wc[k]; }
        acc = warp_reduce(acc);
        if (lane == 0) sv[r] = acc;
    }
    __syncthreads();

    // stage 2: u[r] = W1[r,:].v   (8 warps x 32 rows each)
    for (int r = wid; r < IND; r += 8) {
        const float* row = W1 + (size_t)r * HID;
        float acc = 0.0f;
#pragma unroll
        for (int i = 0; i < 4; i++) { int k = lane + i * 32; acc += row[k] * sv[k]; }
        acc = warp_reduce(acc);
        if (lane == 0) g_u[r] = acc;
    }

    // scalars (warps 0 and 1)
    if (wid == 0) {
        float acc = 0.0f;
#pragma unroll
        for (int i = 0; i < 4; i++) { int k = lane + i * 32; acc += b1[k] * sv[k]; }
        acc = warp_reduce(acc);
        if (lane == 0) g_b1v = acc;
    } else if (wid == 1) {
        float acc = 0.0f;
#pragma unroll
        for (int i = 0; i < 4; i++) { int k = lane + i * 32; acc += b2[k] * Wc[k]; }
        acc = warp_reduce(acc);
        if (lane == 0) g_b2c = acc + bc[0];
    }
}

// ---------------- fused: degree scatter (blocks < NE4) + GEMV t = x@u ----------------
// GEMV: half-warp per row -> 4 independent float4 loads per thread (2x MLP).
__global__ void deg_gemv_kernel(const int* __restrict__ ei,
                                const float* __restrict__ ew,
                                const float* __restrict__ x) {
    if (blockIdx.x < NE4) {
        int idx = blockIdx.x * 256 + threadIdx.x;
        if (idx >= EE / 4) return;
        int e4 = idx * 4;
        float4 w4 = *(const float4*)(ew + e4);
        if (g_is64 == 0) {
            int4 d4 = *(const int4*)(ei + EE + e4);
            if ((unsigned)d4.x < NN) atomicAdd(&g_deg[d4.x], w4.x);
            if ((unsigned)d4.y < NN) atomicAdd(&g_deg[d4.y], w4.y);
            if ((unsigned)d4.z < NN) atomicAdd(&g_deg[d4.z], w4.z);
            if ((unsigned)d4.w < NN) atomicAdd(&g_deg[d4.w], w4.w);
        } else {
            const float* wp = &w4.x;
#pragma unroll
            for (int j = 0; j < 4; j++) {
                int d = edge_dst64(ei, e4 + j);
                if ((unsigned)d < NN) atomicAdd(&g_deg[d], wp[j]);
            }
        }
    } else {
        __shared__ float su[IND];
        int tid = threadIdx.x;
        su[tid] = g_u[tid];
        __syncthreads();

        int lane = tid & 31;
        int lane16 = lane & 15;
        int half = lane >> 4;                         // 0 or 1
        int row = (blockIdx.x - NE4) * 16 + (tid >> 5) * 2 + half;
        if (row >= NN) return;

        const float4* xp = (const float4*)(x + (size_t)row * IND);
        float acc = 0.0f;
#pragma unroll
        for (int i = 0; i < 4; i++) {                 // 4 independent 16B loads
            int c = lane16 + i * 16;                  // float4 index 0..63
            float4 xv = xp[c];
            acc += xv.x * su[c * 4 + 0] + xv.y * su[c * 4 + 1]
                 + xv.z * su[c * 4 + 2] + xv.w * su[c * 4 + 3];
        }
        acc = half_reduce(acc);
        if (lane16 == 0) g_t[row] = acc;
    }
}

// ---------------- dinv + premultiply: dinv = rsqrt(deg), tt = t*dinv ----------------
__global__ void dinv_kernel() {
    int i = blockIdx.x * blockDim.x + threadIdx.x;
    if (i < NN) {
        float dv = rsqrtf(g_deg[i]);
        g_dinv[i] = dv;
        g_tt[i] = g_t[i] * dv;
    }
}

// ---------------- edge scatter: dst += ew * srcvec[src]  (4 edges/thread) ----------------
template <int PASS>   // PASS=1: g_tt -> g_s ; PASS=2: g_ss -> g_z
__global__ void scatter_kernel(const int* __restrict__ ei,
                               const float* __restrict__ ew) {
    int idx = blockIdx.x * 256 + threadIdx.x;
    if (idx >= EE / 4) return;
    int e4 = idx * 4;
    const float* srcvec = (PASS == 1) ? g_tt : g_ss;
    float* dstvec = (PASS == 1) ? g_s : g_z;
    float4 w4 = *(const float4*)(ew + e4);
    if (g_is64 == 0) {
        int4 s4 = *(const int4*)(ei + e4);
        int4 d4 = *(const int4*)(ei + EE + e4);
        if ((unsigned)s4.x < NN && (unsigned)d4.x < NN) atomicAdd(&dstvec[d4.x], w4.x * srcvec[s4.x]);
        if ((unsigned)s4.y < NN && (unsigned)d4.y < NN) atomicAdd(&dstvec[d4.y], w4.y * srcvec[s4.y]);
        if ((unsigned)s4.z < NN && (unsigned)d4.z < NN) atomicAdd(&dstvec[d4.z], w4.z * srcvec[s4.z]);
        if ((unsigned)s4.w < NN && (unsigned)d4.w < NN) atomicAdd(&dstvec[d4.w], w4.w * srcvec[s4.w]);
    } else {
        const float* wp = &w4.x;
#pragma unroll
        for (int j = 0; j < 4; j++) {
            int s = edge_src64(ei, e4 + j);
            int d = edge_dst64(ei, e4 + j);
            if ((unsigned)s < NN && (unsigned)d < NN)
                atomicAdd(&dstvec[d], wp[j] * srcvec[s]);
        }
    }
}

// ---------------- finalizers ----------------
__global__ void fin1_kernel() {
    int i = blockIdx.x * blockDim.x + threadIdx.x;
    if (i < NN) {
        float dv = g_dinv[i];
        float s = dv * (g_s[i] + g_tt[i]) + g_b1v;
        g_ss[i] = dv * s;
    }
}

__global__ void fin2_kernel(float* __restrict__ out) {
    int i = blockIdx.x * blockDim.x + threadIdx.x;
    if (i < NN) out[i] = g_dinv[i] * (g_z[i] + g_ss[i]) + g_b2c;
}

// ---------------- launch ----------------
extern "C" void kernel_launch(void* const* d_in, const int* in_sizes, int n_in,
                              void* d_out, int out_size) {
    const float* x  = (const float*)d_in[0];
    const int*   ei = (const int*)d_in[1];   // int32 OR int64 (detected on device)
    const float* ew = (const float*)d_in[2];
    const float* W1 = (const float*)d_in[3];
    const float* b1 = (const float*)d_in[4];
    const float* W2 = (const float*)d_in[5];
    const float* b2 = (const float*)d_in[6];
    const float* Wc = (const float*)d_in[7];
    const float* bc = (const float*)d_in[8];
    float* out      = (float*)d_out;

    const int TB = 256;
    const int nb_n = (NN + TB - 1) / TB;

    init_kernel<<<nb_n, TB>>>(ei);                         // + dtype probe
    weights_kernel<<<1, TB>>>(W1, b1, W2, b2, Wc, bc);     // u, b1v, b2c (warp-row dots)

    // degree atomics overlapped with t = x@u (independent work, one kernel)
    deg_gemv_kernel<<<NE4 + NBG, TB>>>(ei, ew, x);
    dinv_kernel<<<nb_n, TB>>>();                           // dinv + tt = t*dinv

    // layer 1: s_raw[d] += ew * tt[src]; finalize -> ss
    scatter_kernel<1><<<NE4, TB>>>(ei, ew);
    fin1_kernel<<<nb_n, TB>>>();

    // layer 2 + head: z_raw[d] += ew * ss[src]; out = dinv*(z+ss) + b2c
    scatter_kernel<2><<<NE4, TB>>>(ei, ew);
    fin2_kernel<<<nb_n, TB>>>(out);
}

// round 12
// speedup vs baseline: 1.1881x; 1.1881x over previous
#include <cuda_runtime.h>
#include <cstddef>

// Problem constants (fixed by the reference)
#define NN 50000
#define EE 800000
#define IND 256
#define HID 128
#define NE4 ((EE / 4 + 255) / 256)   // 782 edge blocks, 4 edges/thread
#define NBG (NN / 16)                // 3125 gemv blocks, 16 rows/block (half-warp per row)

// ---------------- scratch (no allocation allowed) ----------------
__device__ int   g_is64;          // 1 if edge_index is int64, 0 if int32
__device__ float g_deg[NN];
__device__ float g_dinv[NN];
__device__ float g_t[NN];         // t = x @ u  (raw)
__device__ float g_tt[NN];        // tt = dinv * t
__device__ float g_s[NN];         // scatter1 accumulator (raw)
__device__ float g_ss[NN];        // ss = dinv * s_final
__device__ float g_z[NN];         // scatter2 accumulator (raw)
__device__ float g_v[HID];        // v = W2 @ Wc
__device__ float g_u[IND];        // u = W1 @ v
__device__ float g_b1v;           // b1 . v
__device__ float g_b2c;           // b2 . Wc + bc

__device__ __forceinline__ int edge_src64(const int* p, int e) { return p[2 * e]; }
__device__ __forceinline__ int edge_dst64(const int* p, int e) { return p[2 * (EE + e)]; }

__device__ __forceinline__ float warp_reduce(float v) {
#pragma unroll
    for (int off = 16; off > 0; off >>= 1)
        v += __shfl_xor_sync(0xFFFFFFFFu, v, off);
    return v;
}
__device__ __forceinline__ float half_reduce(float v) {   // reduce within 16-lane group
#pragma unroll
    for (int off = 8; off > 0; off >>= 1)
        v += __shfl_xor_sync(0xFFFFFFFFu, v, off);
    return v;
}

// ---------------- init + dtype probe (block 0) ----------------
__global__ void init_kernel(const int* __restrict__ ei) {
    int i = blockIdx.x * blockDim.x + threadIdx.x;
    if (i < NN) {
        g_deg[i] = 1.0f;   // self-loop weight
        g_s[i] = 0.0f;
        g_z[i] = 0.0f;
    }
    if (blockIdx.x == 0) {
        __shared__ int nz;
        if (threadIdx.x == 0) nz = 0;
        __syncthreads();
        int v = ei[2 * threadIdx.x + 1];   // odd words: 0 iff int64 layout
        if (v != 0) atomicAdd(&nz, 1);
        __syncthreads();
        if (threadIdx.x == 0) g_is64 = (nz < 8) ? 1 : 0;
    }
}

// ---------------- weight collapse stage 1: v = W2 @ Wc (warp/row, multi-block) ----------------
__global__ void weights1_kernel(const float* __restrict__ W2,
                                const float* __restrict__ Wc,
                                const float* __restrict__ b2,
                                const float* __restrict__ bc) {
    int warp = blockIdx.x * 8 + (threadIdx.x >> 5);
    int lane = threadIdx.x & 31;
    if (warp < HID) {
        const float* row = W2 + (size_t)warp * HID;
        float acc = 0.0f;
#pragma unroll
        for (int i = 0; i < 4; i++) { int k = lane + i * 32; acc += row[k] * Wc[k]; }
        acc = warp_reduce(acc);
        if (lane == 0) g_v[warp] = acc;
    } else if (warp == HID) {
        float acc = 0.0f;
#pragma unroll
        for (int i = 0; i < 4; i++) { int k = lane + i * 32; acc += b2[k] * Wc[k]; }
        acc = warp_reduce(acc);
        if (lane == 0) g_b2c = acc + bc[0];
    }
}

// ---------------- weight collapse stage 2: u = W1 @ v (warp/row, multi-block) ----------------
__global__ void weights2_kernel(const float* __restrict__ W1,
                                const float* __restrict__ b1) {
    int warp = blockIdx.x * 8 + (threadIdx.x >> 5);
    int lane = threadIdx.x & 31;
    if (warp < IND) {
        const float* row = W1 + (size_t)warp * HID;
        float acc = 0.0f;
#pragma unroll
        for (int i = 0; i < 4; i++) { int k = lane + i * 32; acc += row[k] * g_v[k]; }
        acc = warp_reduce(acc);
        if (lane == 0) g_u[warp] = acc;
    } else if (warp == IND) {
        float acc = 0.0f;
#pragma unroll
        for (int i = 0; i < 4; i++) { int k = lane + i * 32; acc += b1[k] * g_v[k]; }
        acc = warp_reduce(acc);
        if (lane == 0) g_b1v = acc;
    }
}

// ---------------- fused: degree scatter (blocks < NE4) + GEMV t = x@u ----------------
// GEMV: half-warp per row -> 4 independent float4 loads per thread.
__global__ void deg_gemv_kernel(const int* __restrict__ ei,
                                const float* __restrict__ ew,
                                const float* __restrict__ x) {
    if (blockIdx.x < NE4) {
        int idx = blockIdx.x * 256 + threadIdx.x;
        if (idx >= EE / 4) return;
        int e4 = idx * 4;
        float4 w4 = *(const float4*)(ew + e4);
        if (g_is64 == 0) {
            int4 d4 = *(const int4*)(ei + EE + e4);
            if ((unsigned)d4.x < NN) atomicAdd(&g_deg[d4.x], w4.x);
            if ((unsigned)d4.y < NN) atomicAdd(&g_deg[d4.y], w4.y);
            if ((unsigned)d4.z < NN) atomicAdd(&g_deg[d4.z], w4.z);
            if ((unsigned)d4.w < NN) atomicAdd(&g_deg[d4.w], w4.w);
        } else {
            const float* wp = &w4.x;
#pragma unroll
            for (int j = 0; j < 4; j++) {
                int d = edge_dst64(ei, e4 + j);
                if ((unsigned)d < NN) atomicAdd(&g_deg[d], wp[j]);
            }
        }
    } else {
        __shared__ float su[IND];
        int tid = threadIdx.x;
        su[tid] = g_u[tid];
        __syncthreads();

        int lane = tid & 31;
        int lane16 = lane & 15;
        int half = lane >> 4;                         // 0 or 1
        int row = (blockIdx.x - NE4) * 16 + (tid >> 5) * 2 + half;
        if (row >= NN) return;

        const float4* xp = (const float4*)(x + (size_t)row * IND);
        float acc = 0.0f;
#pragma unroll
        for (int i = 0; i < 4; i++) {                 // 4 independent 16B loads
            int c = lane16 + i * 16;                  // float4 index 0..63
            float4 xv = xp[c];
            acc += xv.x * su[c * 4 + 0] + xv.y * su[c * 4 + 1]
                 + xv.z * su[c * 4 + 2] + xv.w * su[c * 4 + 3];
        }
        acc = half_reduce(acc);
        if (lane16 == 0) g_t[row] = acc;
    }
}

// ---------------- dinv + premultiply: dinv = rsqrt(deg), tt = t*dinv ----------------
__global__ void dinv_kernel() {
    int i = blockIdx.x * blockDim.x + threadIdx.x;
    if (i < NN) {
        float dv = rsqrtf(g_deg[i]);
        g_dinv[i] = dv;
        g_tt[i] = g_t[i] * dv;
    }
}

// ---------------- edge scatter: dst += ew * srcvec[src]  (4 edges/thread) ----------------
template <int PASS>   // PASS=1: g_tt -> g_s ; PASS=2: g_ss -> g_z
__global__ void scatter_kernel(const int* __restrict__ ei,
                               const float* __restrict__ ew) {
    int idx = blockIdx.x * 256 + threadIdx.x;
    if (idx >= EE / 4) return;
    int e4 = idx * 4;
    const float* srcvec = (PASS == 1) ? g_tt : g_ss;
    float* dstvec = (PASS == 1) ? g_s : g_z;
    float4 w4 = *(const float4*)(ew + e4);
    if (g_is64 == 0) {
        int4 s4 = *(const int4*)(ei + e4);
        int4 d4 = *(const int4*)(ei + EE + e4);
        if ((unsigned)s4.x < NN && (unsigned)d4.x < NN) atomicAdd(&dstvec[d4.x], w4.x * srcvec[s4.x]);
        if ((unsigned)s4.y < NN && (unsigned)d4.y < NN) atomicAdd(&dstvec[d4.y], w4.y * srcvec[s4.y]);
        if ((unsigned)s4.z < NN && (unsigned)d4.z < NN) atomicAdd(&dstvec[d4.z], w4.z * srcvec[s4.z]);
        if ((unsigned)s4.w < NN && (unsigned)d4.w < NN) atomicAdd(&dstvec[d4.w], w4.w * srcvec[s4.w]);
    } else {
        const float* wp = &w4.x;
#pragma unroll
        for (int j = 0; j < 4; j++) {
            int s = edge_src64(ei, e4 + j);
            int d = edge_dst64(ei, e4 + j);
            if ((unsigned)s < NN && (unsigned)d < NN)
                atomicAdd(&dstvec[d], wp[j] * srcvec[s]);
        }
    }
}

// ---------------- finalizers ----------------
__global__ void fin1_kernel() {
    int i = blockIdx.x * blockDim.x + threadIdx.x;
    if (i < NN) {
        float dv = g_dinv[i];
        float s = dv * (g_s[i] + g_tt[i]) + g_b1v;
        g_ss[i] = dv * s;
    }
}

__global__ void fin2_kernel(float* __restrict__ out) {
    int i = blockIdx.x * blockDim.x + threadIdx.x;
    if (i < NN) out[i] = g_dinv[i] * (g_z[i] + g_ss[i]) + g_b2c;
}

// ---------------- launch ----------------
extern "C" void kernel_launch(void* const* d_in, const int* in_sizes, int n_in,
                              void* d_out, int out_size) {
    const float* x  = (const float*)d_in[0];
    const int*   ei = (const int*)d_in[1];   // int32 OR int64 (detected on device)
    const float* ew = (const float*)d_in[2];
    const float* W1 = (const float*)d_in[3];
    const float* b1 = (const float*)d_in[4];
    const float* W2 = (const float*)d_in[5];
    const float* b2 = (const float*)d_in[6];
    const float* Wc = (const float*)d_in[7];
    const float* bc = (const float*)d_in[8];
    float* out      = (float*)d_out;

    const int TB = 256;
    const int nb_n = (NN + TB - 1) / TB;

    init_kernel<<<nb_n, TB>>>(ei);                 // + dtype probe
    weights1_kernel<<<17, TB>>>(W2, Wc, b2, bc);   // v = W2@Wc, b2.Wc+bc  (multi-block)
    weights2_kernel<<<33, TB>>>(W1, b1);           // u = W1@v,  b1.v      (multi-block)

    // degree atomics overlapped with t = x@u (independent work, one kernel)
    deg_gemv_kernel<<<NE4 + NBG, TB>>>(ei, ew, x);
    dinv_kernel<<<nb_n, TB>>>();                   // dinv + tt = t*dinv

    // layer 1: s_raw[d] += ew * tt[src]; finalize -> ss
    scatter_kernel<1><<<NE4, TB>>>(ei, ew);
    fin1_kernel<<<nb_n, TB>>>();

    // layer 2 + head: z_raw[d] += ew * ss[src]; out = dinv*(z+ss) + b2c
    scatter_kernel<2><<<NE4, TB>>>(ei, ew);
    fin2_kernel<<<nb_n, TB>>>(out);
}